// round 1
// baseline (speedup 1.0000x reference)
#include <cuda_runtime.h>

#define D_MODEL 2048
#define SEQ_L   256
#define BATCH_N 128

// Fused taps: g0[d] = k0[d] + D[d], g1[d] = k1[d]
__device__ float g_tap0[D_MODEL];
__device__ float g_tap1[D_MODEL];

struct cdbl { double re, im; };
__device__ __forceinline__ cdbl cmul(cdbl a, cdbl b) {
    return { a.re*b.re - a.im*b.im, a.re*b.im + a.im*b.re };
}
__device__ __forceinline__ cdbl cadd(cdbl a, cdbl b) {
    return { a.re + b.re, a.im + b.im };
}
__device__ __forceinline__ cdbl cdiv(cdbl a, cdbl b) {
    double den = b.re*b.re + b.im*b.im;
    return { (a.re*b.re + a.im*b.im)/den, (a.im*b.re - a.re*b.im)/den };
}

// One thread per channel d. h = 2 modes.
// dA = [[p0, -1], [-1, p1]],  p_j = (1 + A_j/2) / (1 - A_j/2)
// P = dA^256 via 8 repeated squarings (matches jnp matrix_power schedule for 2^8).
// k0 = Re( C0 * ((1-P00)*B0 + (-P01)*B1) )
// k1 = Re( C1 * ((-P10)*B0 + (1-P11)*B1) )
__global__ void compute_taps_kernel(const float* __restrict__ A_real,
                                    const float* __restrict__ A_imag,
                                    const float* __restrict__ B_real,
                                    const float* __restrict__ B_imag,
                                    const float* __restrict__ C_real,
                                    const float* __restrict__ C_imag,
                                    const float* __restrict__ Dvec) {
    int d = blockIdx.x * blockDim.x + threadIdx.x;
    if (d >= D_MODEL) return;

    cdbl A0 = { -exp((double)A_real[d*2 + 0]), (double)A_imag[d*2 + 0] };
    cdbl A1 = { -exp((double)A_real[d*2 + 1]), (double)A_imag[d*2 + 1] };

    cdbl p0 = cdiv({1.0 + 0.5*A0.re,  0.5*A0.im},
                   {1.0 - 0.5*A0.re, -0.5*A0.im});
    cdbl p1 = cdiv({1.0 + 0.5*A1.re,  0.5*A1.im},
                   {1.0 - 0.5*A1.re, -0.5*A1.im});

    cdbl m00 = p0, m01 = {-1.0, 0.0}, m10 = {-1.0, 0.0}, m11 = p1;
    #pragma unroll
    for (int s = 0; s < 8; s++) {          // M <- M^2, eight times => M^256
        cdbl n00 = cadd(cmul(m00, m00), cmul(m01, m10));
        cdbl n01 = cadd(cmul(m00, m01), cmul(m01, m11));
        cdbl n10 = cadd(cmul(m10, m00), cmul(m11, m10));
        cdbl n11 = cadd(cmul(m10, m01), cmul(m11, m11));
        m00 = n00; m01 = n01; m10 = n10; m11 = n11;
    }

    cdbl B0 = { (double)B_real[d*2 + 0], (double)B_imag[d*2 + 0] };
    cdbl B1 = { (double)B_real[d*2 + 1], (double)B_imag[d*2 + 1] };
    cdbl C0 = { (double)C_real[d*2 + 0], (double)C_imag[d*2 + 0] };
    cdbl C1 = { (double)C_real[d*2 + 1], (double)C_imag[d*2 + 1] };

    cdbl t0 = cadd(cmul({1.0 - m00.re, -m00.im}, B0),
                   cmul({     -m01.re, -m01.im}, B1));
    cdbl t1 = cadd(cmul({     -m10.re, -m10.im}, B0),
                   cmul({1.0 - m11.re, -m11.im}, B1));

    float k0 = (float)(C0.re*t0.re - C0.im*t0.im);
    float k1 = (float)(C1.re*t1.re - C1.im*t1.im);

    g_tap0[d] = k0 + Dvec[d];
    g_tap1[d] = k1;
}

// out[b,t,d] = g0[d]*u[b,t,d] + g1[d]*u[b,t-1,d]   (second term dropped at t==0)
// Layout (b, L, d), d fastest -> fully coalesced float4 streaming.
__global__ void conv2tap_kernel(const float* __restrict__ u,
                                float* __restrict__ out) {
    unsigned int idx = blockIdx.x * blockDim.x + threadIdx.x;   // float4 index
    unsigned int i = idx << 2;                                   // element index
    int d = (int)(i & (D_MODEL - 1));
    int t = (int)((i >> 11) & (SEQ_L - 1));                      // 2048 = 2^11

    float4 uv = *reinterpret_cast<const float4*>(u + i);
    float4 g0 = *reinterpret_cast<const float4*>(g_tap0 + d);
    float4 g1 = *reinterpret_cast<const float4*>(g_tap1 + d);

    float4 up;
    if (t == 0) {
        up = make_float4(0.f, 0.f, 0.f, 0.f);
    } else {
        up = *reinterpret_cast<const float4*>(u + i - D_MODEL);
    }

    float4 o;
    o.x = fmaf(g0.x, uv.x, g1.x * up.x);
    o.y = fmaf(g0.y, uv.y, g1.y * up.y);
    o.z = fmaf(g0.z, uv.z, g1.z * up.z);
    o.w = fmaf(g0.w, uv.w, g1.w * up.w);

    *reinterpret_cast<float4*>(out + i) = o;
}

extern "C" void kernel_launch(void* const* d_in, const int* in_sizes, int n_in,
                              void* d_out, int out_size) {
    const float* u      = (const float*)d_in[0];
    const float* A_real = (const float*)d_in[1];
    const float* A_imag = (const float*)d_in[2];
    const float* B_real = (const float*)d_in[3];
    const float* B_imag = (const float*)d_in[4];
    const float* C_real = (const float*)d_in[5];
    const float* C_imag = (const float*)d_in[6];
    const float* Dvec   = (const float*)d_in[7];
    float* out = (float*)d_out;

    compute_taps_kernel<<<(D_MODEL + 255) / 256, 256>>>(
        A_real, A_imag, B_real, B_imag, C_real, C_imag, Dvec);

    const unsigned int total_f4 = (unsigned int)BATCH_N * SEQ_L * D_MODEL / 4; // 16,777,216
    conv2tap_kernel<<<total_f4 / 256, 256>>>(u, out);
}

// round 2
// speedup vs baseline: 1.1214x; 1.1214x over previous
#include <cuda_runtime.h>

#define D_MODEL 2048
#define SEQ_L   256
#define BATCH_N 128

// Fused taps: g0[d] = k0[d] + D[d], g1[d] = k1[d]
__device__ float g_tap0[D_MODEL];
__device__ float g_tap1[D_MODEL];

struct cdbl { double re, im; };
__device__ __forceinline__ cdbl cmul(cdbl a, cdbl b) {
    return { a.re*b.re - a.im*b.im, a.re*b.im + a.im*b.re };
}
__device__ __forceinline__ cdbl cadd(cdbl a, cdbl b) {
    return { a.re + b.re, a.im + b.im };
}
__device__ __forceinline__ cdbl cdiv(cdbl a, cdbl b) {
    double inv = 1.0 / (b.re*b.re + b.im*b.im);   // one division instead of two
    return { (a.re*b.re + a.im*b.im)*inv, (a.im*b.re - a.re*b.im)*inv };
}

// One thread per channel d. h = 2 modes.
// dA = [[p0, -1], [-1, p1]],  p_j = (1 + A_j/2) / (1 - A_j/2)
// P = dA^256 via 8 repeated squarings (matches jnp matrix_power schedule for 2^8).
// 64 blocks x 32 threads: spread the FP64 work over 64 SMs (was 8 SMs -> ~20us;
// FP64 budget ~18.4 lanes/SM/cyc makes per-SM concentration the bottleneck).
__global__ void compute_taps_kernel(const float* __restrict__ A_real,
                                    const float* __restrict__ A_imag,
                                    const float* __restrict__ B_real,
                                    const float* __restrict__ B_imag,
                                    const float* __restrict__ C_real,
                                    const float* __restrict__ C_imag,
                                    const float* __restrict__ Dvec) {
    int d = blockIdx.x * blockDim.x + threadIdx.x;
    if (d >= D_MODEL) return;

    cdbl A0 = { -exp((double)A_real[d*2 + 0]), (double)A_imag[d*2 + 0] };
    cdbl A1 = { -exp((double)A_real[d*2 + 1]), (double)A_imag[d*2 + 1] };

    cdbl p0 = cdiv({1.0 + 0.5*A0.re,  0.5*A0.im},
                   {1.0 - 0.5*A0.re, -0.5*A0.im});
    cdbl p1 = cdiv({1.0 + 0.5*A1.re,  0.5*A1.im},
                   {1.0 - 0.5*A1.re, -0.5*A1.im});

    cdbl m00 = p0, m01 = {-1.0, 0.0}, m10 = {-1.0, 0.0}, m11 = p1;
    #pragma unroll
    for (int s = 0; s < 8; s++) {          // M <- M^2, eight times => M^256
        cdbl n00 = cadd(cmul(m00, m00), cmul(m01, m10));
        cdbl n01 = cadd(cmul(m00, m01), cmul(m01, m11));
        cdbl n10 = cadd(cmul(m10, m00), cmul(m11, m10));
        cdbl n11 = cadd(cmul(m10, m01), cmul(m11, m11));
        m00 = n00; m01 = n01; m10 = n10; m11 = n11;
    }

    cdbl B0 = { (double)B_real[d*2 + 0], (double)B_imag[d*2 + 0] };
    cdbl B1 = { (double)B_real[d*2 + 1], (double)B_imag[d*2 + 1] };
    cdbl C0 = { (double)C_real[d*2 + 0], (double)C_imag[d*2 + 0] };
    cdbl C1 = { (double)C_real[d*2 + 1], (double)C_imag[d*2 + 1] };

    cdbl t0 = cadd(cmul({1.0 - m00.re, -m00.im}, B0),
                   cmul({     -m01.re, -m01.im}, B1));
    cdbl t1 = cadd(cmul({     -m10.re, -m10.im}, B0),
                   cmul({1.0 - m11.re, -m11.im}, B1));

    float k0 = (float)(C0.re*t0.re - C0.im*t0.im);
    float k1 = (float)(C1.re*t1.re - C1.im*t1.im);

    g_tap0[d] = k0 + Dvec[d];
    g_tap1[d] = k1;
}

// out[b,t,d] = g0[d]*u[b,t,d] + g1[d]*u[b,t-1,d]   (second term dropped at t==0)
// Layout (b, L, d), d fastest -> fully coalesced float4 streaming.
// Measured at DRAM roofline (6.28 TB/s achieved on 512 MB traffic) -> unchanged.
__global__ void conv2tap_kernel(const float* __restrict__ u,
                                float* __restrict__ out) {
    unsigned int idx = blockIdx.x * blockDim.x + threadIdx.x;   // float4 index
    unsigned int i = idx << 2;                                   // element index
    int d = (int)(i & (D_MODEL - 1));
    int t = (int)((i >> 11) & (SEQ_L - 1));                      // 2048 = 2^11

    float4 uv = *reinterpret_cast<const float4*>(u + i);
    float4 g0 = *reinterpret_cast<const float4*>(g_tap0 + d);
    float4 g1 = *reinterpret_cast<const float4*>(g_tap1 + d);

    float4 up;
    if (t == 0) {
        up = make_float4(0.f, 0.f, 0.f, 0.f);
    } else {
        up = *reinterpret_cast<const float4*>(u + i - D_MODEL);
    }

    float4 o;
    o.x = fmaf(g0.x, uv.x, g1.x * up.x);
    o.y = fmaf(g0.y, uv.y, g1.y * up.y);
    o.z = fmaf(g0.z, uv.z, g1.z * up.z);
    o.w = fmaf(g0.w, uv.w, g1.w * up.w);

    *reinterpret_cast<float4*>(out + i) = o;
}

extern "C" void kernel_launch(void* const* d_in, const int* in_sizes, int n_in,
                              void* d_out, int out_size) {
    const float* u      = (const float*)d_in[0];
    const float* A_real = (const float*)d_in[1];
    const float* A_imag = (const float*)d_in[2];
    const float* B_real = (const float*)d_in[3];
    const float* B_imag = (const float*)d_in[4];
    const float* C_real = (const float*)d_in[5];
    const float* C_imag = (const float*)d_in[6];
    const float* Dvec   = (const float*)d_in[7];
    float* out = (float*)d_out;

    // 64 blocks x 32 threads: one warp per SM across 64 SMs.
    compute_taps_kernel<<<64, 32>>>(
        A_real, A_imag, B_real, B_imag, C_real, C_imag, Dvec);

    const unsigned int total_f4 = (unsigned int)BATCH_N * SEQ_L * D_MODEL / 4; // 16,777,216
    conv2tap_kernel<<<total_f4 / 256, 256>>>(u, out);
}

// round 4
// speedup vs baseline: 1.2368x; 1.1029x over previous
#include <cuda_runtime.h>

#define D_MODEL 2048
#define SEQ_L   256
#define BATCH_N 128
#define CHUNK   128           // channels per block

struct cf { float re, im; };
__device__ __forceinline__ cf cmulf(cf a, cf b) {
    return { a.re*b.re - a.im*b.im, a.re*b.im + a.im*b.re };
}
__device__ __forceinline__ cf caddf(cf a, cf b) { return { a.re + b.re, a.im + b.im }; }
__device__ __forceinline__ cf cdivf(cf a, cf b) {
    float inv = 1.0f / (b.re*b.re + b.im*b.im);
    return { (a.re*b.re + a.im*b.im)*inv, (a.im*b.re - a.re*b.im)*inv };
}

// Single fused kernel.
// Phase 1 (threads 0..127): fp32 taps for this block's 128 channels -> smem.
//   dA = [[p0,-1],[-1,p1]] symmetric; track m00,m01,m11 through 8 squarings (=^256).
// Phase 2 (all 256 threads): t-major streaming conv.
//   warp w owns t in [w*32,(w+1)*32), lane owns one float4 column of the chunk.
//   u[t-1] is carried in a register -> no L2 re-read.
__global__ __launch_bounds__(256) void s4d_fused_kernel(
    const float* __restrict__ u,
    const float* __restrict__ A_real, const float* __restrict__ A_imag,
    const float* __restrict__ B_real, const float* __restrict__ B_imag,
    const float* __restrict__ C_real, const float* __restrict__ C_imag,
    const float* __restrict__ Dvec,
    float* __restrict__ out)
{
    __shared__ float s_g0[CHUNK];
    __shared__ float s_g1[CHUNK];

    const int tid    = threadIdx.x;
    const int chunk0 = blockIdx.x * CHUNK;

    if (tid < CHUNK) {
        const int d = chunk0 + tid;
        const float a0r = -expf(A_real[2*d]),   a0i = A_imag[2*d];
        const float a1r = -expf(A_real[2*d+1]), a1i = A_imag[2*d+1];

        cf p0 = cdivf({1.f + 0.5f*a0r,  0.5f*a0i},
                      {1.f - 0.5f*a0r, -0.5f*a0i});
        cf p1 = cdivf({1.f + 0.5f*a1r,  0.5f*a1i},
                      {1.f - 0.5f*a1r, -0.5f*a1i});

        cf m00 = p0, m01 = {-1.f, 0.f}, m11 = p1;
        #pragma unroll
        for (int s = 0; s < 8; s++) {           // M <- M^2, symmetric form
            cf m01sq = cmulf(m01, m01);
            cf n00 = caddf(cmulf(m00, m00), m01sq);
            cf n01 = cmulf(m01, caddf(m00, m11));
            cf n11 = caddf(m01sq, cmulf(m11, m11));
            m00 = n00; m01 = n01; m11 = n11;
        }

        cf B0 = { B_real[2*d],   B_imag[2*d]   };
        cf B1 = { B_real[2*d+1], B_imag[2*d+1] };
        cf C0 = { C_real[2*d],   C_imag[2*d]   };
        cf C1 = { C_real[2*d+1], C_imag[2*d+1] };

        cf t0 = caddf(cmulf({1.f - m00.re, -m00.im}, B0),
                      cmulf({     -m01.re, -m01.im}, B1));
        cf t1 = caddf(cmulf({     -m01.re, -m01.im}, B0),
                      cmulf({1.f - m11.re, -m11.im}, B1));

        s_g0[tid] = (C0.re*t0.re - C0.im*t0.im) + Dvec[d];
        s_g1[tid] = (C1.re*t1.re - C1.im*t1.im);
    }
    __syncthreads();

    const int lane = tid & 31;          // float4 column within chunk
    const int w    = tid >> 5;          // t-group
    const int t0i  = w * 32;

    const float4 g0 = *reinterpret_cast<const float4*>(s_g0 + lane*4);
    const float4 g1 = *reinterpret_cast<const float4*>(s_g1 + lane*4);

    const unsigned int base =
        ((unsigned int)blockIdx.y * SEQ_L + (unsigned int)t0i) * D_MODEL
        + (unsigned int)chunk0 + (unsigned int)lane * 4u;

    const float4* __restrict__ up = reinterpret_cast<const float4*>(u + base);
    float4*       __restrict__ op = reinterpret_cast<float4*>(out + base);

    float4 uprev;
    if (t0i == 0) uprev = make_float4(0.f, 0.f, 0.f, 0.f);
    else          uprev = *reinterpret_cast<const float4*>(u + base - D_MODEL);

    #pragma unroll 8
    for (int k = 0; k < 32; k++) {
        float4 uv = up[(unsigned int)k * (D_MODEL/4)];
        float4 o;
        o.x = fmaf(g0.x, uv.x, g1.x * uprev.x);
        o.y = fmaf(g0.y, uv.y, g1.y * uprev.y);
        o.z = fmaf(g0.z, uv.z, g1.z * uprev.z);
        o.w = fmaf(g0.w, uv.w, g1.w * uprev.w);
        op[(unsigned int)k * (D_MODEL/4)] = o;
        uprev = uv;
    }
}

extern "C" void kernel_launch(void* const* d_in, const int* in_sizes, int n_in,
                              void* d_out, int out_size) {
    const float* u      = (const float*)d_in[0];
    const float* A_real = (const float*)d_in[1];
    const float* A_imag = (const float*)d_in[2];
    const float* B_real = (const float*)d_in[3];
    const float* B_imag = (const float*)d_in[4];
    const float* C_real = (const float*)d_in[5];
    const float* C_imag = (const float*)d_in[6];
    const float* Dvec   = (const float*)d_in[7];
    float* out = (float*)d_out;

    dim3 grid(D_MODEL / CHUNK, BATCH_N);   // (16, 128) = 2048 blocks
    s4d_fused_kernel<<<grid, 256>>>(u, A_real, A_imag, B_real, B_imag,
                                    C_real, C_imag, Dvec, out);
}